// round 1
// baseline (speedup 1.0000x reference)
#include <cuda_runtime.h>
#include <cstdint>

// Problem constants
#define NTOK 4096
#define KTOP 64
#define DDIM 1024
#define LLAT 16384

// ---------------- device-global accumulators / scratch ----------------
__device__ double g_e2;                 // sum of squared error
__device__ double g_y2;                 // sum of y^2
__device__ float  g_colsum[DDIM];       // per-column sums of y
__device__ float  g_sae_fallback[(size_t)NTOK * DDIM];  // used only if d_out has no room for sae

// ---------------- zero accumulators (runs every graph replay) ----------------
__global__ void k_zero() {
    int t = blockIdx.x * blockDim.x + threadIdx.x;
    if (t == 0) { g_e2 = 0.0; g_y2 = 0.0; }
    if (t < DDIM) g_colsum[t] = 0.0f;
}

// ---------------- y column stats: colsum[d] += sum_n y[n,d]; g_y2 += sum y^2 ----------------
// grid (8, 8): blockIdx.x -> 128-column group, blockIdx.y -> 512-row chunk
__global__ void k_ystats(const float* __restrict__ y) {
    int d  = blockIdx.x * 128 + threadIdx.x;
    int r0 = blockIdx.y * 512;
    const float* p = y + (size_t)r0 * DDIM + d;
    float s = 0.0f, s2 = 0.0f;
#pragma unroll 8
    for (int r = 0; r < 512; r++) {
        float v = p[(size_t)r * DDIM];
        s  += v;
        s2 += v * v;
    }
    atomicAdd(&g_colsum[d], s);
    __shared__ float sh[128];
    sh[threadIdx.x] = s2;
    __syncthreads();
    for (int o = 64; o > 0; o >>= 1) {
        if (threadIdx.x < o) sh[threadIdx.x] += sh[threadIdx.x + o];
        __syncthreads();
    }
    if (threadIdx.x == 0) atomicAdd(&g_y2, (double)sh[0]);
}

// ---------------- skip GEMM: C[n,d] = sum_j x[n,j] * W_skip[d,j] ----------------
// BM=128, BN=64, BK=16, 256 threads (16x16), thread tile 8x4, reg-prefetch pipeline.
#define BM 128
#define BN 64
#define BK 16

__global__ __launch_bounds__(256) void k_skip_gemm(
    const float* __restrict__ A,   // x       [NTOK, DDIM]
    const float* __restrict__ B,   // W_skip  [DDIM, DDIM] (row d contiguous in j)
    float* __restrict__ C)         // sae_out [NTOK, DDIM]
{
    __shared__ float As[BK][BM];
    __shared__ float Bs[BK][BN];

    const int tid = threadIdx.x;
    const int bm  = blockIdx.y * BM;   // token-row base
    const int bn  = blockIdx.x * BN;   // output-col base (W_skip row base)
    const int tx  = tid & 15;          // 0..15 -> 4-col group
    const int ty  = tid >> 4;          // 0..15 -> 8-row group

    const int lr = tid >> 2;           // load row within tile (0..63)
    const int lc = (tid & 3) * 4;      // load col within tile (k offset, float4)

    float acc[8][4];
#pragma unroll
    for (int i = 0; i < 8; i++)
#pragma unroll
        for (int j = 0; j < 4; j++) acc[i][j] = 0.0f;

    float4 pa0, pa1, pb0;

    const size_t aBase0 = (size_t)(bm + lr) * DDIM + lc;
    const size_t aBase1 = (size_t)(bm + 64 + lr) * DDIM + lc;
    const size_t bBase  = (size_t)(bn + lr) * DDIM + lc;

    // prologue: load tile 0
    pa0 = *(const float4*)(A + aBase0);
    pa1 = *(const float4*)(A + aBase1);
    pb0 = *(const float4*)(B + bBase);

    const int nKB = DDIM / BK;   // 64
    for (int kb = 0; kb < nKB; kb++) {
        // store prefetched regs -> smem (transposed to [k][m])
        As[lc + 0][lr]      = pa0.x; As[lc + 1][lr]      = pa0.y;
        As[lc + 2][lr]      = pa0.z; As[lc + 3][lr]      = pa0.w;
        As[lc + 0][lr + 64] = pa1.x; As[lc + 1][lr + 64] = pa1.y;
        As[lc + 2][lr + 64] = pa1.z; As[lc + 3][lr + 64] = pa1.w;
        Bs[lc + 0][lr]      = pb0.x; Bs[lc + 1][lr]      = pb0.y;
        Bs[lc + 2][lr]      = pb0.z; Bs[lc + 3][lr]      = pb0.w;
        __syncthreads();

        // prefetch next tile while computing this one
        if (kb + 1 < nKB) {
            const size_t ko = (size_t)(kb + 1) * BK;
            pa0 = *(const float4*)(A + aBase0 + ko);
            pa1 = *(const float4*)(A + aBase1 + ko);
            pb0 = *(const float4*)(B + bBase  + ko);
        }

#pragma unroll
        for (int k = 0; k < BK; k++) {
            float4 a0 = *(const float4*)&As[k][ty * 8];
            float4 a1 = *(const float4*)&As[k][ty * 8 + 4];
            float4 b0 = *(const float4*)&Bs[k][tx * 4];
            float a[8] = {a0.x, a0.y, a0.z, a0.w, a1.x, a1.y, a1.z, a1.w};
            float b[4] = {b0.x, b0.y, b0.z, b0.w};
#pragma unroll
            for (int i = 0; i < 8; i++)
#pragma unroll
                for (int j = 0; j < 4; j++)
                    acc[i][j] = fmaf(a[i], b[j], acc[i][j]);
        }
        __syncthreads();
    }

    // write back
#pragma unroll
    for (int i = 0; i < 8; i++) {
        int row = bm + ty * 8 + i;
        float4 o = make_float4(acc[i][0], acc[i][1], acc[i][2], acc[i][3]);
        *(float4*)(C + (size_t)row * DDIM + bn + tx * 4) = o;
    }
}

// ---------------- decoder gather + bias + squared-error reduction ----------------
// one CTA per token; 256 threads, each owns 4 contiguous output columns (float4)
__global__ __launch_bounds__(256) void k_decode(
    const float* __restrict__ latent_acts,     // [NTOK, KTOP]
    const int*   __restrict__ latent_indices,  // [NTOK, KTOP]
    const float* __restrict__ W_dec,           // [LLAT, DDIM]
    const float* __restrict__ b_dec,           // [DDIM]
    const float* __restrict__ post_enc,        // [LLAT]
    const float* __restrict__ post_enc_scale,  // [LLAT]
    const float* __restrict__ y,               // [NTOK, DDIM]
    float* __restrict__ sae)                   // [NTOK, DDIM] (contains skip term)
{
    const int n = blockIdx.x;
    const int t = threadIdx.x;

    __shared__ float s_act[KTOP];
    __shared__ int   s_idx[KTOP];

    if (t < KTOP) {
        int i = latent_indices[n * KTOP + t];
        s_idx[t] = i;
        s_act[t] = (latent_acts[n * KTOP + t] + post_enc[i]) * post_enc_scale[i];
    }
    __syncthreads();

    const int d = t * 4;
    float4 acc = *(const float4*)(sae + (size_t)n * DDIM + d);
    float4 bd  = *(const float4*)(b_dec + d);
    acc.x += bd.x; acc.y += bd.y; acc.z += bd.z; acc.w += bd.w;

#pragma unroll 8
    for (int k = 0; k < KTOP; k++) {
        const float4 w = *(const float4*)(W_dec + (size_t)s_idx[k] * DDIM + d);
        const float a = s_act[k];
        acc.x = fmaf(a, w.x, acc.x);
        acc.y = fmaf(a, w.y, acc.y);
        acc.z = fmaf(a, w.z, acc.z);
        acc.w = fmaf(a, w.w, acc.w);
    }
    *(float4*)(sae + (size_t)n * DDIM + d) = acc;

    float4 yv = *(const float4*)(y + (size_t)n * DDIM + d);
    float ex = yv.x - acc.x, ey = yv.y - acc.y, ez = yv.z - acc.z, ew = yv.w - acc.w;
    float e2 = ex * ex + ey * ey + ez * ez + ew * ew;

    __shared__ float sh[256];
    sh[t] = e2;
    __syncthreads();
    for (int o = 128; o > 0; o >>= 1) {
        if (t < o) sh[t] += sh[t + o];
        __syncthreads();
    }
    if (t == 0) atomicAdd(&g_e2, (double)sh[0]);
}

// ---------------- finalize fvu ----------------
__global__ void k_finalize(float* __restrict__ out_fvu) {
    __shared__ float sh[256];
    int t = threadIdx.x;
    float s = 0.0f;
    for (int dd = t; dd < DDIM; dd += 256) {
        float c = g_colsum[dd];
        s += c * c;
    }
    sh[t] = s;
    __syncthreads();
    for (int o = 128; o > 0; o >>= 1) {
        if (t < o) sh[t] += sh[t + o];
        __syncthreads();
    }
    if (t == 0) {
        double tv  = g_y2 - (double)sh[0] / (double)NTOK;
        double fvu = g_e2 / tv;
        out_fvu[0] = (float)fvu;
    }
}

// ---------------- launcher ----------------
extern "C" void kernel_launch(void* const* d_in, const int* in_sizes, int n_in,
                              void* d_out, int out_size) {
    const float* x   = (const float*)d_in[0];
    const float* y   = (const float*)d_in[1];
    const float* la  = (const float*)d_in[2];
    const int*   li  = (const int*)  d_in[3];
    const float* Wd  = (const float*)d_in[4];
    const float* bd  = (const float*)d_in[5];
    const float* pe  = (const float*)d_in[6];
    const float* pes = (const float*)d_in[7];
    const float* Ws  = (const float*)d_in[8];

    float* out = (float*)d_out;
    const size_t ND = (size_t)NTOK * DDIM;

    float* sae = out;
    float* fvu_out = nullptr;
    if ((size_t)out_size >= ND) {
        sae = out;
        if ((size_t)out_size > ND) fvu_out = out + ND;
    } else {
        // harness only wants the fvu scalar: use device scratch for sae
        void* p = nullptr;
        cudaGetSymbolAddress(&p, g_sae_fallback);
        sae = (float*)p;
        fvu_out = out;
    }

    k_zero<<<4, 256>>>();
    k_ystats<<<dim3(8, 8), 128>>>(y);
    k_skip_gemm<<<dim3(DDIM / BN, NTOK / BM), 256>>>(x, Ws, sae);
    k_decode<<<NTOK, 256>>>(la, li, Wd, bd, pe, pes, y, sae);
    if (fvu_out) k_finalize<<<1, 256>>>(fvu_out);
}

// round 3
// speedup vs baseline: 1.6213x; 1.6213x over previous
#include <cuda_runtime.h>
#include <cuda_bf16.h>
#include <mma.h>
#include <cstdint>

using namespace nvcuda;

// Problem constants
#define NTOK 4096
#define KTOP 64
#define DDIM 1024
#define LLAT 16384

// ===================== device globals =====================
__device__ double g_e2;
__device__ double g_y2;
__device__ float  g_colsum[DDIM];
__device__ float  g_sae_fallback[(size_t)NTOK * DDIM];

// split-bf16 copies of x and W_skip
__device__ __nv_bfloat16 g_xhi[(size_t)NTOK * DDIM];
__device__ __nv_bfloat16 g_xlo[(size_t)NTOK * DDIM];
__device__ __nv_bfloat16 g_whi[(size_t)DDIM * DDIM];
__device__ __nv_bfloat16 g_wlo[(size_t)DDIM * DDIM];

// ===================== cp.async helpers (sm_80+, no 'a' features) =====================
__device__ __forceinline__ uint32_t smem_u32(const void* p) {
    uint32_t a;
    asm("{ .reg .u64 t; cvta.to.shared.u64 t, %1; cvt.u32.u64 %0, t; }" : "=r"(a) : "l"(p));
    return a;
}
#define CP_ASYNC16(dst_u32, src_ptr) \
    asm volatile("cp.async.cg.shared.global [%0], [%1], 16;" :: "r"(dst_u32), "l"(src_ptr))
#define CP_ASYNC_COMMIT() asm volatile("cp.async.commit_group;")
#define CP_ASYNC_WAIT1()  asm volatile("cp.async.wait_group 1;")
#define CP_ASYNC_WAIT0()  asm volatile("cp.async.wait_group 0;")

// ===================== zero accumulators =====================
__global__ void k_zero() {
    int t = blockIdx.x * blockDim.x + threadIdx.x;
    if (t == 0) { g_e2 = 0.0; g_y2 = 0.0; }
    if (t < DDIM) g_colsum[t] = 0.0f;
}

// ===================== y column stats =====================
__global__ void k_ystats(const float* __restrict__ y) {
    int d  = blockIdx.x * 128 + threadIdx.x;
    int r0 = blockIdx.y * 512;
    const float* p = y + (size_t)r0 * DDIM + d;
    float s = 0.0f, s2 = 0.0f;
#pragma unroll 8
    for (int r = 0; r < 512; r++) {
        float v = p[(size_t)r * DDIM];
        s  += v;
        s2 += v * v;
    }
    atomicAdd(&g_colsum[d], s);
    __shared__ float sh[128];
    sh[threadIdx.x] = s2;
    __syncthreads();
    for (int o = 64; o > 0; o >>= 1) {
        if (threadIdx.x < o) sh[threadIdx.x] += sh[threadIdx.x + o];
        __syncthreads();
    }
    if (threadIdx.x == 0) atomicAdd(&g_y2, (double)sh[0]);
}

// ===================== fp32 -> bf16 hi/lo split =====================
struct bf16x4 { __nv_bfloat162 a, b; };

__global__ __launch_bounds__(256) void k_split(const float* __restrict__ src,
                                               __nv_bfloat16* __restrict__ hi,
                                               __nv_bfloat16* __restrict__ lo,
                                               int n4) {
    int i = blockIdx.x * blockDim.x + threadIdx.x;
    if (i >= n4) return;
    float4 v = ((const float4*)src)[i];
    __nv_bfloat16 h0 = __float2bfloat16(v.x);
    __nv_bfloat16 h1 = __float2bfloat16(v.y);
    __nv_bfloat16 h2 = __float2bfloat16(v.z);
    __nv_bfloat16 h3 = __float2bfloat16(v.w);
    __nv_bfloat16 l0 = __float2bfloat16(v.x - __bfloat162float(h0));
    __nv_bfloat16 l1 = __float2bfloat16(v.y - __bfloat162float(h1));
    __nv_bfloat16 l2 = __float2bfloat16(v.z - __bfloat162float(h2));
    __nv_bfloat16 l3 = __float2bfloat16(v.w - __bfloat162float(h3));
    bf16x4 ph; ph.a = __halves2bfloat162(h0, h1); ph.b = __halves2bfloat162(h2, h3);
    bf16x4 pl; pl.a = __halves2bfloat162(l0, l1); pl.b = __halves2bfloat162(l2, l3);
    ((bf16x4*)hi)[i] = ph;
    ((bf16x4*)lo)[i] = pl;
}

// ===================== WMMA bf16x3 skip GEMM =====================
// C[m, n] = sum_k x[m,k] * W_skip[n,k] with C = AhBh + AhBl + AlBh (fp32 accum)
// BM=128, BN=128, BK=32, 256 threads = 8 warps (4 M x 2 N), warp tile 32x64.
#define BM 128
#define BN 128
#define BK 32
#define NKB (DDIM / BK)          // 32
#define LDS_PAD 40               // bf16 elements per smem row (80B, conflict-free LDSM)
#define MAT_BYTES (128 * LDS_PAD * 2)       // 10240
#define A_HI_OFF 0
#define A_LO_OFF (MAT_BYTES)
#define B_HI_OFF (2 * MAT_BYTES)
#define B_LO_OFF (3 * MAT_BYTES)
#define STAGE_BYTES (4 * MAT_BYTES)         // 40960
#define GEMM_SMEM (2 * STAGE_BYTES)         // 81920

// per-stage loader: 512 16B-units per matrix, 4 matrices, 256 threads -> 8 cp.async each
__device__ __forceinline__ void load_stage(
    char* st, uint32_t st_u32,
    const __nv_bfloat16* __restrict__ Ahi, const __nv_bfloat16* __restrict__ Alo,
    const __nv_bfloat16* __restrict__ Bhi, const __nv_bfloat16* __restrict__ Blo,
    int bm, int bn, int kb, int tid)
{
    const int k0 = kb * BK;
#pragma unroll
    for (int i = 0; i < 2; i++) {
        int idx  = i * 256 + tid;          // 0..511
        int row  = idx >> 2;               // 0..127
        int unit = idx & 3;                // 16B unit -> 8 bf16
        uint32_t dst = st_u32 + row * (LDS_PAD * 2) + unit * 16;
        size_t   ga  = ((size_t)(bm + row) * DDIM + k0 + unit * 8);
        size_t   gb  = ((size_t)(bn + row) * DDIM + k0 + unit * 8);
        CP_ASYNC16(dst + A_HI_OFF, Ahi + ga);
        CP_ASYNC16(dst + A_LO_OFF, Alo + ga);
        CP_ASYNC16(dst + B_HI_OFF, Bhi + gb);
        CP_ASYNC16(dst + B_LO_OFF, Blo + gb);
    }
}

__global__ __launch_bounds__(256, 2) void k_skip_gemm_wmma(
    const __nv_bfloat16* __restrict__ Ahi, const __nv_bfloat16* __restrict__ Alo,
    const __nv_bfloat16* __restrict__ Bhi, const __nv_bfloat16* __restrict__ Blo,
    float* __restrict__ C)
{
    extern __shared__ char smem[];
    const int tid = threadIdx.x;
    const int wid = tid >> 5;
    const int wm  = wid >> 1;     // 0..3 (M)
    const int wn  = wid & 1;      // 0..1 (N)
    const int bm  = blockIdx.y * BM;
    const int bn  = blockIdx.x * BN;
    const uint32_t smem32 = smem_u32(smem);

    wmma::fragment<wmma::accumulator, 16, 16, 16, float> acc[2][4];
#pragma unroll
    for (int mm = 0; mm < 2; mm++)
#pragma unroll
        for (int nn = 0; nn < 4; nn++)
            wmma::fill_fragment(acc[mm][nn], 0.0f);

    // prologue
    load_stage(smem, smem32, Ahi, Alo, Bhi, Blo, bm, bn, 0, tid);
    CP_ASYNC_COMMIT();

    for (int kb = 0; kb < NKB; kb++) {
        const int s = kb & 1;
        if (kb + 1 < NKB) {
            const int f = (kb + 1) & 1;
            load_stage(smem + f * STAGE_BYTES, smem32 + f * STAGE_BYTES,
                       Ahi, Alo, Bhi, Blo, bm, bn, kb + 1, tid);
            CP_ASYNC_COMMIT();
            CP_ASYNC_WAIT1();     // stage kb is complete
        } else {
            CP_ASYNC_WAIT0();
        }
        __syncthreads();

        const __nv_bfloat16* As_hi = (const __nv_bfloat16*)(smem + s * STAGE_BYTES + A_HI_OFF);
        const __nv_bfloat16* As_lo = (const __nv_bfloat16*)(smem + s * STAGE_BYTES + A_LO_OFF);
        const __nv_bfloat16* Bs_hi = (const __nv_bfloat16*)(smem + s * STAGE_BYTES + B_HI_OFF);
        const __nv_bfloat16* Bs_lo = (const __nv_bfloat16*)(smem + s * STAGE_BYTES + B_LO_OFF);

#pragma unroll
        for (int kk = 0; kk < 2; kk++) {
            const int k0 = kk * 16;
            wmma::fragment<wmma::matrix_a, 16, 16, 16, __nv_bfloat16, wmma::row_major> ah[2], al[2];
#pragma unroll
            for (int mm = 0; mm < 2; mm++) {
                const int r0 = wm * 32 + mm * 16;
                wmma::load_matrix_sync(ah[mm], As_hi + r0 * LDS_PAD + k0, LDS_PAD);
                wmma::load_matrix_sync(al[mm], As_lo + r0 * LDS_PAD + k0, LDS_PAD);
            }
#pragma unroll
            for (int nn = 0; nn < 4; nn++) {
                const int c0 = wn * 64 + nn * 16;
                wmma::fragment<wmma::matrix_b, 16, 16, 16, __nv_bfloat16, wmma::col_major> bh, bl;
                wmma::load_matrix_sync(bh, Bs_hi + c0 * LDS_PAD + k0, LDS_PAD);
                wmma::load_matrix_sync(bl, Bs_lo + c0 * LDS_PAD + k0, LDS_PAD);
#pragma unroll
                for (int mm = 0; mm < 2; mm++) {
                    wmma::mma_sync(acc[mm][nn], ah[mm], bh, acc[mm][nn]);
                    wmma::mma_sync(acc[mm][nn], ah[mm], bl, acc[mm][nn]);
                    wmma::mma_sync(acc[mm][nn], al[mm], bh, acc[mm][nn]);
                }
            }
        }
        __syncthreads();   // all warps done with stage s before it is refilled
    }

    // epilogue: store fp32 tiles
#pragma unroll
    for (int mm = 0; mm < 2; mm++) {
        const int row0 = bm + wm * 32 + mm * 16;
#pragma unroll
        for (int nn = 0; nn < 4; nn++) {
            const int col0 = bn + wn * 64 + nn * 16;
            wmma::store_matrix_sync(C + (size_t)row0 * DDIM + col0, acc[mm][nn],
                                    DDIM, wmma::mem_row_major);
        }
    }
}

// ===================== decoder gather + bias + e2 =====================
__global__ __launch_bounds__(256) void k_decode(
    const float* __restrict__ latent_acts,
    const int*   __restrict__ latent_indices,
    const float* __restrict__ W_dec,
    const float* __restrict__ b_dec,
    const float* __restrict__ post_enc,
    const float* __restrict__ post_enc_scale,
    const float* __restrict__ y,
    float* __restrict__ sae)
{
    const int n = blockIdx.x;
    const int t = threadIdx.x;

    __shared__ float s_act[KTOP];
    __shared__ int   s_idx[KTOP];

    if (t < KTOP) {
        int i = latent_indices[n * KTOP + t];
        s_idx[t] = i;
        s_act[t] = (latent_acts[n * KTOP + t] + post_enc[i]) * post_enc_scale[i];
    }
    __syncthreads();

    const int d = t * 4;
    float4 acc = *(const float4*)(sae + (size_t)n * DDIM + d);
    float4 bd  = *(const float4*)(b_dec + d);
    acc.x += bd.x; acc.y += bd.y; acc.z += bd.z; acc.w += bd.w;

#pragma unroll 8
    for (int k = 0; k < KTOP; k++) {
        const float4 w = *(const float4*)(W_dec + (size_t)s_idx[k] * DDIM + d);
        const float a = s_act[k];
        acc.x = fmaf(a, w.x, acc.x);
        acc.y = fmaf(a, w.y, acc.y);
        acc.z = fmaf(a, w.z, acc.z);
        acc.w = fmaf(a, w.w, acc.w);
    }
    *(float4*)(sae + (size_t)n * DDIM + d) = acc;

    float4 yv = *(const float4*)(y + (size_t)n * DDIM + d);
    float ex = yv.x - acc.x, ey = yv.y - acc.y, ez = yv.z - acc.z, ew = yv.w - acc.w;
    float e2 = ex * ex + ey * ey + ez * ez + ew * ew;

    __shared__ float sh[256];
    sh[t] = e2;
    __syncthreads();
    for (int o = 128; o > 0; o >>= 1) {
        if (t < o) sh[t] += sh[t + o];
        __syncthreads();
    }
    if (t == 0) atomicAdd(&g_e2, (double)sh[0]);
}

// ===================== finalize fvu =====================
__global__ void k_finalize(float* __restrict__ out_fvu) {
    __shared__ float sh[256];
    int t = threadIdx.x;
    float s = 0.0f;
    for (int dd = t; dd < DDIM; dd += 256) {
        float c = g_colsum[dd];
        s += c * c;
    }
    sh[t] = s;
    __syncthreads();
    for (int o = 128; o > 0; o >>= 1) {
        if (t < o) sh[t] += sh[t + o];
        __syncthreads();
    }
    if (t == 0) {
        double tv  = g_y2 - (double)sh[0] / (double)NTOK;
        double fvu = g_e2 / tv;
        out_fvu[0] = (float)fvu;
    }
}

// ===================== launcher =====================
extern "C" void kernel_launch(void* const* d_in, const int* in_sizes, int n_in,
                              void* d_out, int out_size) {
    const float* x   = (const float*)d_in[0];
    const float* y   = (const float*)d_in[1];
    const float* la  = (const float*)d_in[2];
    const int*   li  = (const int*)  d_in[3];
    const float* Wd  = (const float*)d_in[4];
    const float* bd  = (const float*)d_in[5];
    const float* pe  = (const float*)d_in[6];
    const float* pes = (const float*)d_in[7];
    const float* Ws  = (const float*)d_in[8];

    float* out = (float*)d_out;
    const size_t ND = (size_t)NTOK * DDIM;

    float* sae = out;
    float* fvu_out = nullptr;
    if ((size_t)out_size >= ND) {
        sae = out;
        if ((size_t)out_size > ND) fvu_out = out + ND;
    } else {
        void* p = nullptr;
        cudaGetSymbolAddress(&p, g_sae_fallback);
        sae = (float*)p;
        fvu_out = out;
    }

    void *pxh, *pxl, *pwh, *pwl;
    cudaGetSymbolAddress(&pxh, g_xhi);
    cudaGetSymbolAddress(&pxl, g_xlo);
    cudaGetSymbolAddress(&pwh, g_whi);
    cudaGetSymbolAddress(&pwl, g_wlo);

    cudaFuncSetAttribute(k_skip_gemm_wmma, cudaFuncAttributeMaxDynamicSharedMemorySize, GEMM_SMEM);

    k_zero<<<4, 256>>>();
    k_ystats<<<dim3(8, 8), 128>>>(y);
    k_split<<<(NTOK * DDIM / 4 + 255) / 256, 256>>>(x,  (__nv_bfloat16*)pxh, (__nv_bfloat16*)pxl, NTOK * DDIM / 4);
    k_split<<<(DDIM * DDIM / 4 + 255) / 256, 256>>>(Ws, (__nv_bfloat16*)pwh, (__nv_bfloat16*)pwl, DDIM * DDIM / 4);
    k_skip_gemm_wmma<<<dim3(DDIM / BN, NTOK / BM), 256, GEMM_SMEM>>>(
        (const __nv_bfloat16*)pxh, (const __nv_bfloat16*)pxl,
        (const __nv_bfloat16*)pwh, (const __nv_bfloat16*)pwl, sae);
    k_decode<<<NTOK, 256>>>(la, li, Wd, bd, pe, pes, y, sae);
    if (fvu_out) k_finalize<<<1, 256>>>(fvu_out);
}

// round 4
// speedup vs baseline: 2.5316x; 1.5614x over previous
#include <cuda_runtime.h>
#include <cuda_fp16.h>
#include <mma.h>
#include <cstdint>

using namespace nvcuda;

// Problem constants
#define NTOK 4096
#define KTOP 64
#define DDIM 1024
#define LLAT 16384

// ===================== device globals =====================
__device__ double g_e2;
__device__ double g_y2;
__device__ float  g_colsum[DDIM];
__device__ float  g_sae_fallback[(size_t)NTOK * DDIM];

// fp16 copies
__device__ __half g_xh [(size_t)NTOK * DDIM];   // x
__device__ __half g_wh [(size_t)DDIM * DDIM];   // W_skip
__device__ __half g_wdh[(size_t)LLAT * DDIM];   // W_dec

// ===================== helpers =====================
__device__ __forceinline__ uint32_t smem_u32(const void* p) {
    uint32_t a;
    asm("{ .reg .u64 t; cvta.to.shared.u64 t, %1; cvt.u32.u64 %0, t; }" : "=r"(a) : "l"(p));
    return a;
}
#define CP_ASYNC16(dst_u32, src_ptr) \
    asm volatile("cp.async.cg.shared.global [%0], [%1], 16;" :: "r"(dst_u32), "l"(src_ptr))
#define CP_ASYNC_COMMIT() asm volatile("cp.async.commit_group;")
#define CP_ASYNC_WAIT1()  asm volatile("cp.async.wait_group 1;")
#define CP_ASYNC_WAIT0()  asm volatile("cp.async.wait_group 0;")

// ===================== zero accumulators =====================
__global__ void k_zero() {
    int t = blockIdx.x * blockDim.x + threadIdx.x;
    if (t == 0) { g_e2 = 0.0; g_y2 = 0.0; }
    if (t < DDIM) g_colsum[t] = 0.0f;
}

// ===================== y column stats =====================
__global__ void k_ystats(const float* __restrict__ y) {
    int d  = blockIdx.x * 128 + threadIdx.x;
    int r0 = blockIdx.y * 512;
    const float* p = y + (size_t)r0 * DDIM + d;
    float s = 0.0f, s2 = 0.0f;
#pragma unroll 8
    for (int r = 0; r < 512; r++) {
        float v = p[(size_t)r * DDIM];
        s  += v;
        s2 += v * v;
    }
    atomicAdd(&g_colsum[d], s);
    __shared__ float sh[128];
    sh[threadIdx.x] = s2;
    __syncthreads();
    for (int o = 64; o > 0; o >>= 1) {
        if (threadIdx.x < o) sh[threadIdx.x] += sh[threadIdx.x + o];
        __syncthreads();
    }
    if (threadIdx.x == 0) atomicAdd(&g_y2, (double)sh[0]);
}

// ===================== fp32 -> fp16 convert =====================
__global__ __launch_bounds__(256) void k_tohalf(const float* __restrict__ src,
                                                __half* __restrict__ dst, int n4) {
    int i = blockIdx.x * blockDim.x + threadIdx.x;
    if (i >= n4) return;
    float4 v = ((const float4*)src)[i];
    __half2 lo = __floats2half2_rn(v.x, v.y);
    __half2 hi = __floats2half2_rn(v.z, v.w);
    uint2 o;
    o.x = *(uint32_t*)&lo;
    o.y = *(uint32_t*)&hi;
    ((uint2*)dst)[i] = o;
}

// ===================== WMMA fp16 single-pass skip GEMM =====================
// C[m, n] = sum_k x[m,k] * W_skip[n,k], fp16 inputs, fp32 accum.
// BM=128, BN=128, BK=64, 256 threads = 8 warps (4 M x 2 N), warp tile 32x64.
#define BM 128
#define BN 128
#define BK 64
#define NKB (DDIM / BK)          // 16
#define LDS_PAD 72               // halves per smem row (144B, LDSM conflict-free)
#define MAT_BYTES (128 * LDS_PAD * 2)       // 18432
#define A_OFF 0
#define B_OFF (MAT_BYTES)
#define STAGE_BYTES (2 * MAT_BYTES)         // 36864
#define GEMM_SMEM (2 * STAGE_BYTES)         // 73728

// 2048 16B units per stage (A:1024 + B:1024), 256 threads -> 8 cp.async each
__device__ __forceinline__ void load_stage(
    uint32_t st_u32,
    const __half* __restrict__ A, const __half* __restrict__ B,
    int bm, int bn, int kb, int tid)
{
    const int k0 = kb * BK;
#pragma unroll
    for (int i = 0; i < 4; i++) {
        int idx  = i * 256 + tid;          // 0..1023
        int row  = idx >> 3;               // 0..127
        int unit = idx & 7;                // 16B unit -> 8 halves
        uint32_t dst = st_u32 + row * (LDS_PAD * 2) + unit * 16;
        CP_ASYNC16(dst + A_OFF, A + ((size_t)(bm + row) * DDIM + k0 + unit * 8));
        CP_ASYNC16(dst + B_OFF, B + ((size_t)(bn + row) * DDIM + k0 + unit * 8));
    }
}

__global__ __launch_bounds__(256, 2) void k_skip_gemm_wmma(
    const __half* __restrict__ A, const __half* __restrict__ B,
    float* __restrict__ C)
{
    extern __shared__ char smem[];
    const int tid = threadIdx.x;
    const int wid = tid >> 5;
    const int wm  = wid >> 1;     // 0..3 (M)
    const int wn  = wid & 1;      // 0..1 (N)
    const int bm  = blockIdx.y * BM;
    const int bn  = blockIdx.x * BN;
    const uint32_t smem32 = smem_u32(smem);

    wmma::fragment<wmma::accumulator, 16, 16, 16, float> acc[2][4];
#pragma unroll
    for (int mm = 0; mm < 2; mm++)
#pragma unroll
        for (int nn = 0; nn < 4; nn++)
            wmma::fill_fragment(acc[mm][nn], 0.0f);

    // prologue
    load_stage(smem32, A, B, bm, bn, 0, tid);
    CP_ASYNC_COMMIT();

    for (int kb = 0; kb < NKB; kb++) {
        const int s = kb & 1;
        if (kb + 1 < NKB) {
            const int f = (kb + 1) & 1;
            load_stage(smem32 + f * STAGE_BYTES, A, B, bm, bn, kb + 1, tid);
            CP_ASYNC_COMMIT();
            CP_ASYNC_WAIT1();
        } else {
            CP_ASYNC_WAIT0();
        }
        __syncthreads();

        const __half* As = (const __half*)(smem + s * STAGE_BYTES + A_OFF);
        const __half* Bs = (const __half*)(smem + s * STAGE_BYTES + B_OFF);

#pragma unroll
        for (int kk = 0; kk < 4; kk++) {
            const int k0 = kk * 16;
            wmma::fragment<wmma::matrix_a, 16, 16, 16, __half, wmma::row_major> af[2];
#pragma unroll
            for (int mm = 0; mm < 2; mm++)
                wmma::load_matrix_sync(af[mm], As + (wm * 32 + mm * 16) * LDS_PAD + k0, LDS_PAD);
#pragma unroll
            for (int nn = 0; nn < 4; nn++) {
                wmma::fragment<wmma::matrix_b, 16, 16, 16, __half, wmma::col_major> bf;
                wmma::load_matrix_sync(bf, Bs + (wn * 64 + nn * 16) * LDS_PAD + k0, LDS_PAD);
#pragma unroll
                for (int mm = 0; mm < 2; mm++)
                    wmma::mma_sync(acc[mm][nn], af[mm], bf, acc[mm][nn]);
            }
        }
        __syncthreads();
    }

    // epilogue
#pragma unroll
    for (int mm = 0; mm < 2; mm++) {
        const int row0 = bm + wm * 32 + mm * 16;
#pragma unroll
        for (int nn = 0; nn < 4; nn++) {
            const int col0 = bn + wn * 64 + nn * 16;
            wmma::store_matrix_sync(C + (size_t)row0 * DDIM + col0, acc[mm][nn],
                                    DDIM, wmma::mem_row_major);
        }
    }
}

// ===================== decoder gather (fp16 W_dec) + bias + e2 =====================
__global__ __launch_bounds__(256) void k_decode(
    const float* __restrict__ latent_acts,
    const int*   __restrict__ latent_indices,
    const __half* __restrict__ W_dec,          // fp16 [LLAT, DDIM]
    const float* __restrict__ b_dec,
    const float* __restrict__ post_enc,
    const float* __restrict__ post_enc_scale,
    const float* __restrict__ y,
    float* __restrict__ sae)
{
    const int n = blockIdx.x;
    const int t = threadIdx.x;

    __shared__ float s_act[KTOP];
    __shared__ int   s_idx[KTOP];

    if (t < KTOP) {
        int i = latent_indices[n * KTOP + t];
        s_idx[t] = i;
        s_act[t] = (latent_acts[n * KTOP + t] + post_enc[i]) * post_enc_scale[i];
    }
    __syncthreads();

    const int d = t * 4;
    float4 acc = *(const float4*)(sae + (size_t)n * DDIM + d);
    float4 bd  = *(const float4*)(b_dec + d);
    acc.x += bd.x; acc.y += bd.y; acc.z += bd.z; acc.w += bd.w;

#pragma unroll 8
    for (int k = 0; k < KTOP; k++) {
        uint2 wraw = *(const uint2*)(W_dec + (size_t)s_idx[k] * DDIM + d);
        float2 w0 = __half22float2(*(const __half2*)&wraw.x);
        float2 w1 = __half22float2(*(const __half2*)&wraw.y);
        const float a = s_act[k];
        acc.x = fmaf(a, w0.x, acc.x);
        acc.y = fmaf(a, w0.y, acc.y);
        acc.z = fmaf(a, w1.x, acc.z);
        acc.w = fmaf(a, w1.y, acc.w);
    }
    *(float4*)(sae + (size_t)n * DDIM + d) = acc;

    float4 yv = *(const float4*)(y + (size_t)n * DDIM + d);
    float ex = yv.x - acc.x, ey = yv.y - acc.y, ez = yv.z - acc.z, ew = yv.w - acc.w;
    float e2 = ex * ex + ey * ey + ez * ez + ew * ew;

    __shared__ float sh[256];
    sh[t] = e2;
    __syncthreads();
    for (int o = 128; o > 0; o >>= 1) {
        if (t < o) sh[t] += sh[t + o];
        __syncthreads();
    }
    if (t == 0) atomicAdd(&g_e2, (double)sh[0]);
}

// ===================== finalize fvu =====================
__global__ void k_finalize(float* __restrict__ out_fvu) {
    __shared__ float sh[256];
    int t = threadIdx.x;
    float s = 0.0f;
    for (int dd = t; dd < DDIM; dd += 256) {
        float c = g_colsum[dd];
        s += c * c;
    }
    sh[t] = s;
    __syncthreads();
    for (int o = 128; o > 0; o >>= 1) {
        if (t < o) sh[t] += sh[t + o];
        __syncthreads();
    }
    if (t == 0) {
        double tv  = g_y2 - (double)sh[0] / (double)NTOK;
        double fvu = g_e2 / tv;
        out_fvu[0] = (float)fvu;
    }
}

// ===================== launcher =====================
extern "C" void kernel_launch(void* const* d_in, const int* in_sizes, int n_in,
                              void* d_out, int out_size) {
    const float* x   = (const float*)d_in[0];
    const float* y   = (const float*)d_in[1];
    const float* la  = (const float*)d_in[2];
    const int*   li  = (const int*)  d_in[3];
    const float* Wd  = (const float*)d_in[4];
    const float* bd  = (const float*)d_in[5];
    const float* pe  = (const float*)d_in[6];
    const float* pes = (const float*)d_in[7];
    const float* Ws  = (const float*)d_in[8];

    float* out = (float*)d_out;
    const size_t ND = (size_t)NTOK * DDIM;

    float* sae = out;
    float* fvu_out = nullptr;
    if ((size_t)out_size >= ND) {
        sae = out;
        if ((size_t)out_size > ND) fvu_out = out + ND;
    } else {
        void* p = nullptr;
        cudaGetSymbolAddress(&p, g_sae_fallback);
        sae = (float*)p;
        fvu_out = out;
    }

    void *pxh, *pwh, *pwdh;
    cudaGetSymbolAddress(&pxh,  g_xh);
    cudaGetSymbolAddress(&pwh,  g_wh);
    cudaGetSymbolAddress(&pwdh, g_wdh);

    cudaFuncSetAttribute(k_skip_gemm_wmma, cudaFuncAttributeMaxDynamicSharedMemorySize, GEMM_SMEM);

    k_zero<<<4, 256>>>();
    k_ystats<<<dim3(8, 8), 128>>>(y);
    k_tohalf<<<(NTOK * DDIM / 4 + 255) / 256, 256>>>(x,  (__half*)pxh,  NTOK * DDIM / 4);
    k_tohalf<<<(DDIM * DDIM / 4 + 255) / 256, 256>>>(Ws, (__half*)pwh,  DDIM * DDIM / 4);
    k_tohalf<<<(LLAT * DDIM / 4 + 255) / 256, 256>>>(Wd, (__half*)pwdh, LLAT * DDIM / 4);
    k_skip_gemm_wmma<<<dim3(DDIM / BN, NTOK / BM), 256, GEMM_SMEM>>>(
        (const __half*)pxh, (const __half*)pwh, sae);
    k_decode<<<NTOK, 256>>>(la, li, (const __half*)pwdh, bd, pe, pes, y, sae);
    if (fvu_out) k_finalize<<<1, 256>>>(fvu_out);
}